// round 1
// baseline (speedup 1.0000x reference)
#include <cuda_runtime.h>

#define BB    16
#define HH    64
#define WW    64
#define HWSZ  4096
#define DIMC  256
#define NQKV  192
#define NHD   8
#define CPHN  8
#define CRN   64
#define SCALEF 0.17677669529663687f

typedef unsigned long long ull;

// Scratch (allocation-free rule: device globals)
__device__ float g_qkv[BB * NQKV * HWSZ];   // (B, 192, 4096)
__device__ float g_y  [BB * CRN  * HWSZ];   // (B, 64, 4096)

__device__ __forceinline__ ull fma2(ull a, ull b, ull c) {
    ull d;
    asm("fma.rn.f32x2 %0, %1, %2, %3;" : "=l"(d) : "l"(a), "l"(b), "l"(c));
    return d;
}
__device__ __forceinline__ ull pack2(float lo, float hi) {
    ull d;
    asm("mov.b64 %0, {%1, %2};" : "=l"(d)
        : "r"(__float_as_uint(lo)), "r"(__float_as_uint(hi)));
    return d;
}

// C(N x 4096) = W(N x K) * X(K x 4096) + bias, per batch (grid.z).
// Tile: 64(n) x 128(m), BK=16, 256 threads, each thread 8n x 4m via f32x2 pairs along n.
__global__ __launch_bounds__(256) void gemm_kernel(
    const float* __restrict__ Wm,   // N x K row-major
    const float* __restrict__ Xm,   // per-batch K x 4096 row-major
    const float* __restrict__ bias, // N
    float* __restrict__ Ym,         // per-batch N x 4096
    int K, long xStride, long yStride)
{
    const int b  = blockIdx.z;
    const int n0 = blockIdx.y * 64;
    const int m0 = blockIdx.x * 128;
    const float* X = Xm + (long)b * xStride;
    float*       Y = Ym + (long)b * yStride;

    __shared__ float sW[16][68];   // [k][n], padded
    __shared__ float sX[16][128];  // [k][m]

    const int tid  = threadIdx.x;
    const int lane = tid & 31;
    const int warp = tid >> 5;
    const int nb   = warp * 8;   // n offset in tile
    const int mb   = lane * 4;   // m offset in tile

    ull acc[4][4];
#pragma unroll
    for (int p = 0; p < 4; p++)
#pragma unroll
        for (int j = 0; j < 4; j++) acc[p][j] = 0ULL;

    for (int k0 = 0; k0 < K; k0 += 16) {
        // W tile: rows n0..n0+63, cols k0..k0+15 -> transposed into sW[k][n]
        {
            int r  = tid >> 2;        // 0..63
            int c4 = (tid & 3) * 4;   // 0,4,8,12
            float4 w = *(const float4*)&Wm[(long)(n0 + r) * K + k0 + c4];
            sW[c4 + 0][r] = w.x;
            sW[c4 + 1][r] = w.y;
            sW[c4 + 2][r] = w.z;
            sW[c4 + 3][r] = w.w;
        }
        // X tile: rows k0..k0+15, cols m0..m0+127
#pragma unroll
        for (int p = 0; p < 2; p++) {
            int idx = tid + p * 256;
            int r   = idx >> 5;        // 0..15
            int c   = (idx & 31) * 4;
            *(float4*)&sX[r][c] = *(const float4*)&X[(long)(k0 + r) * HWSZ + m0 + c];
        }
        __syncthreads();

#pragma unroll
        for (int k = 0; k < 16; k++) {
            float4 xv = *(const float4*)&sX[k][mb];
            ull xd0 = pack2(xv.x, xv.x);
            ull xd1 = pack2(xv.y, xv.y);
            ull xd2 = pack2(xv.z, xv.z);
            ull xd3 = pack2(xv.w, xv.w);
            const ull* wrow = (const ull*)&sW[k][nb];
            ull w0 = wrow[0], w1 = wrow[1], w2 = wrow[2], w3 = wrow[3];
            acc[0][0] = fma2(w0, xd0, acc[0][0]);
            acc[0][1] = fma2(w0, xd1, acc[0][1]);
            acc[0][2] = fma2(w0, xd2, acc[0][2]);
            acc[0][3] = fma2(w0, xd3, acc[0][3]);
            acc[1][0] = fma2(w1, xd0, acc[1][0]);
            acc[1][1] = fma2(w1, xd1, acc[1][1]);
            acc[1][2] = fma2(w1, xd2, acc[1][2]);
            acc[1][3] = fma2(w1, xd3, acc[1][3]);
            acc[2][0] = fma2(w2, xd0, acc[2][0]);
            acc[2][1] = fma2(w2, xd1, acc[2][1]);
            acc[2][2] = fma2(w2, xd2, acc[2][2]);
            acc[2][3] = fma2(w2, xd3, acc[2][3]);
            acc[3][0] = fma2(w3, xd0, acc[3][0]);
            acc[3][1] = fma2(w3, xd1, acc[3][1]);
            acc[3][2] = fma2(w3, xd2, acc[3][2]);
            acc[3][3] = fma2(w3, xd3, acc[3][3]);
        }
        __syncthreads();
    }

#pragma unroll
    for (int p = 0; p < 4; p++) {
        int n_lo = n0 + nb + 2 * p;
        float blo = bias[n_lo], bhi = bias[n_lo + 1];
#pragma unroll
        for (int j = 0; j < 4; j++) {
            float lo = __uint_as_float((unsigned)(acc[p][j] & 0xffffffffu));
            float hi = __uint_as_float((unsigned)(acc[p][j] >> 32));
            long m = m0 + mb + j;
            Y[(long)n_lo * HWSZ + m]       = lo + blo;
            Y[(long)(n_lo + 1) * HWSZ + m] = hi + bhi;
        }
    }
}

// Fused slide attention: unfold-shift + learned depthwise 3x3 + bias + rpb,
// q.k softmax over 9 taps, attn-weighted v. One block = (b, head, 8-row tile).
__global__ __launch_bounds__(256) void attn_kernel(
    const float* __restrict__ qkv,  // (B, 192, 4096)
    const float* __restrict__ w1,   // (72, 9) learned depthwise weights
    const float* __restrict__ dcb,  // (72) unfold bias
    const float* __restrict__ dc1b, // (72) conv1 bias
    const float* __restrict__ rpb,  // (NH*9)
    float* __restrict__ y)          // (B, 64, 4096)
{
    const int b  = blockIdx.z;
    const int hd = blockIdx.y;
    const int h0 = blockIdx.x * 8;

    __shared__ float skk[8][10][66];
    __shared__ float svv[8][10][66];
    __shared__ float sw1[648];
    __shared__ float sdcb[72];
    __shared__ float srpb[9];

    const int tid = threadIdx.x;
    for (int i = tid; i < 648; i += 256) sw1[i] = w1[i];
    for (int i = tid; i < 72; i += 256) sdcb[i] = dcb[i] + dc1b[i];
    if (tid < 9) srpb[tid] = rpb[hd * 9 + tid];

    const float* base = qkv + ((long)b * NQKV + hd * 24) * HWSZ;

    // Halo tiles for kk (ch 8..15) and vv (ch 16..23), zero-padded.
    for (int i = tid; i < 8 * 10 * 66; i += 256) {
        int c   = i / 660;
        int rem = i - c * 660;
        int yy  = rem / 66;
        int xx  = rem - yy * 66;
        int gh  = h0 + yy - 1;
        int gw  = xx - 1;
        float kv = 0.f, vv = 0.f;
        if (gh >= 0 && gh < 64 && gw >= 0 && gw < 64) {
            long off = (long)(8 + c) * HWSZ + gh * 64 + gw;
            kv = base[off];
            vv = base[off + 8 * HWSZ];
        }
        skk[c][yy][xx] = kv;
        svv[c][yy][xx] = vv;
    }
    __syncthreads();

    for (int pos = tid; pos < 512; pos += 256) {
        int hl = pos >> 6;
        int w  = pos & 63;
        int hw = (h0 + hl) * 64 + w;

        float q[8], qsum = 0.f;
#pragma unroll
        for (int c = 0; c < 8; c++) {
            q[c] = base[(long)c * HWSZ + hw] * SCALEF;
            qsum += q[c];
        }

        float logit[9];
#pragma unroll
        for (int t = 0; t < 9; t++) logit[t] = qsum * srpb[t];

#pragma unroll
        for (int c = 0; c < 8; c++) {
            float n[9];
#pragma unroll
            for (int ty = 0; ty < 3; ty++)
#pragma unroll
                for (int tx = 0; tx < 3; tx++)
                    n[ty * 3 + tx] = skk[c][hl + ty][w + tx];
            float qc = q[c];
            const float* wc = &sw1[c * 81];
#pragma unroll
            for (int t = 0; t < 9; t++) {
                float kv = n[t] + sdcb[c * 9 + t];
#pragma unroll
                for (int i = 0; i < 9; i++) kv += wc[t * 9 + i] * n[i];
                logit[t] += qc * kv;
            }
        }

        // softmax over 9 taps
        float m = logit[0];
#pragma unroll
        for (int t = 1; t < 9; t++) m = fmaxf(m, logit[t]);
        float at[9], s = 0.f;
#pragma unroll
        for (int t = 0; t < 9; t++) { at[t] = __expf(logit[t] - m); s += at[t]; }
        float inv = 1.f / s;
#pragma unroll
        for (int t = 0; t < 9; t++) at[t] *= inv;

        // attn-weighted v
#pragma unroll
        for (int c = 0; c < 8; c++) {
            float n[9];
#pragma unroll
            for (int ty = 0; ty < 3; ty++)
#pragma unroll
                for (int tx = 0; tx < 3; tx++)
                    n[ty * 3 + tx] = svv[c][hl + ty][w + tx];
            float o = 0.f;
            const float* wc = &sw1[c * 81];
#pragma unroll
            for (int t = 0; t < 9; t++) {
                float vv = n[t] + sdcb[c * 9 + t];
#pragma unroll
                for (int i = 0; i < 9; i++) vv += wc[t * 9 + i] * n[i];
                o += at[t] * vv;
            }
            y[((long)b * CRN + hd * 8 + c) * HWSZ + hw] = o;
        }
    }
}

extern "C" void kernel_launch(void* const* d_in, const int* in_sizes, int n_in,
                              void* d_out, int out_size) {
    const float* x      = (const float*)d_in[0];
    // d_in[1]=H22, d_in[2]=W22, d_in[3]=relative_pos_index, d_in[4]=relative_coords_table (unused)
    const float* qkv_w  = (const float*)d_in[5];
    const float* qkv_b  = (const float*)d_in[6];
    const float* dcb    = (const float*)d_in[7];
    const float* w1     = (const float*)d_in[8];
    const float* dc1b   = (const float*)d_in[9];
    const float* rpb    = (const float*)d_in[10];
    const float* proj_w = (const float*)d_in[11];
    const float* proj_b = (const float*)d_in[12];
    float* out = (float*)d_out;

    float *qkv = nullptr, *y = nullptr;
    cudaGetSymbolAddress((void**)&qkv, g_qkv);
    cudaGetSymbolAddress((void**)&y, g_y);

    // qkv = qkv_w (192x256) @ x_b (256x4096) + qkv_b
    gemm_kernel<<<dim3(HWSZ / 128, NQKV / 64, BB), 256>>>(
        qkv_w, x, qkv_b, qkv, DIMC, (long)DIMC * HWSZ, (long)NQKV * HWSZ);

    // fused slide attention -> y (B, 64, 4096)
    attn_kernel<<<dim3(8, NHD, BB), 256>>>(qkv, w1, dcb, dc1b, rpb, y);

    // out = proj_w (256x64) @ y_b (64x4096) + proj_b
    gemm_kernel<<<dim3(HWSZ / 128, DIMC / 64, BB), 256>>>(
        proj_w, y, proj_b, out, CRN, (long)CRN * HWSZ, (long)DIMC * HWSZ);
}

// round 2
// speedup vs baseline: 1.9807x; 1.9807x over previous
#include <cuda_runtime.h>

#define BB    16
#define HWSZ  4096
#define DIMC  256
#define NQKV  192
#define NHD   8
#define CRN   64
#define SCALEF 0.17677669529663687f

typedef unsigned long long ull;

__device__ float g_qkv[BB * NQKV * HWSZ];   // (B, 192, 4096)
__device__ float g_y  [BB * CRN  * HWSZ];   // (B, 64, 4096)

__device__ __forceinline__ ull fma2(ull a, ull b, ull c) {
    ull d;
    asm("fma.rn.f32x2 %0, %1, %2, %3;" : "=l"(d) : "l"(a), "l"(b), "l"(c));
    return d;
}
__device__ __forceinline__ ull pack2(float lo, float hi) {
    ull d;
    asm("mov.b64 %0, {%1, %2};" : "=l"(d)
        : "r"(__float_as_uint(lo)), "r"(__float_as_uint(hi)));
    return d;
}

// C(N x 4096) = W(N x K) * X(K x 4096) + bias, per batch (grid.z).
// 64(n) x 128(m) tile, BK=16, double-buffered smem, f32x2 FMA pairs along n.
__global__ __launch_bounds__(256) void gemm_kernel(
    const float* __restrict__ Wm,
    const float* __restrict__ Xm,
    const float* __restrict__ bias,
    float* __restrict__ Ym,
    int K, long xStride, long yStride)
{
    const int b  = blockIdx.z;
    const int n0 = blockIdx.y * 64;
    const int m0 = blockIdx.x * 128;
    const float* X = Xm + (long)b * xStride;
    float*       Y = Ym + (long)b * yStride;

    __shared__ float sW[2][16][68];
    __shared__ float sX[2][16][128];

    const int tid  = threadIdx.x;
    const int lane = tid & 31;
    const int warp = tid >> 5;
    const int nb   = warp * 8;
    const int mb   = lane * 4;

    const int wr  = tid >> 2;
    const int wc4 = (tid & 3) * 4;
    const int xr0 = tid >> 5;
    const int xc  = (tid & 31) * 4;

    ull acc[4][4];
#pragma unroll
    for (int p = 0; p < 4; p++)
#pragma unroll
        for (int j = 0; j < 4; j++) acc[p][j] = 0ULL;

    const int KT = K / 16;

    // prologue: tile 0
    {
        float4 wf  = *(const float4*)&Wm[(long)(n0 + wr) * K + wc4];
        float4 xf0 = *(const float4*)&X[(long)(xr0)     * HWSZ + m0 + xc];
        float4 xf1 = *(const float4*)&X[(long)(xr0 + 8) * HWSZ + m0 + xc];
        sW[0][wc4 + 0][wr] = wf.x;
        sW[0][wc4 + 1][wr] = wf.y;
        sW[0][wc4 + 2][wr] = wf.z;
        sW[0][wc4 + 3][wr] = wf.w;
        *(float4*)&sX[0][xr0][xc]     = xf0;
        *(float4*)&sX[0][xr0 + 8][xc] = xf1;
    }
    __syncthreads();

    for (int kt = 0; kt < KT; kt++) {
        const int cur = kt & 1;
        float4 wfn, xf0n, xf1n;
        if (kt + 1 < KT) {
            int k0 = (kt + 1) * 16;
            wfn  = *(const float4*)&Wm[(long)(n0 + wr) * K + k0 + wc4];
            xf0n = *(const float4*)&X[(long)(k0 + xr0)     * HWSZ + m0 + xc];
            xf1n = *(const float4*)&X[(long)(k0 + xr0 + 8) * HWSZ + m0 + xc];
        }
#pragma unroll
        for (int k = 0; k < 16; k++) {
            float4 xv = *(const float4*)&sX[cur][k][mb];
            ull xd0 = pack2(xv.x, xv.x);
            ull xd1 = pack2(xv.y, xv.y);
            ull xd2 = pack2(xv.z, xv.z);
            ull xd3 = pack2(xv.w, xv.w);
            const ull* wrow = (const ull*)&sW[cur][k][nb];
            ull w0 = wrow[0], w1 = wrow[1], w2 = wrow[2], w3 = wrow[3];
            acc[0][0] = fma2(w0, xd0, acc[0][0]);
            acc[0][1] = fma2(w0, xd1, acc[0][1]);
            acc[0][2] = fma2(w0, xd2, acc[0][2]);
            acc[0][3] = fma2(w0, xd3, acc[0][3]);
            acc[1][0] = fma2(w1, xd0, acc[1][0]);
            acc[1][1] = fma2(w1, xd1, acc[1][1]);
            acc[1][2] = fma2(w1, xd2, acc[1][2]);
            acc[1][3] = fma2(w1, xd3, acc[1][3]);
            acc[2][0] = fma2(w2, xd0, acc[2][0]);
            acc[2][1] = fma2(w2, xd1, acc[2][1]);
            acc[2][2] = fma2(w2, xd2, acc[2][2]);
            acc[2][3] = fma2(w2, xd3, acc[2][3]);
            acc[3][0] = fma2(w3, xd0, acc[3][0]);
            acc[3][1] = fma2(w3, xd1, acc[3][1]);
            acc[3][2] = fma2(w3, xd2, acc[3][2]);
            acc[3][3] = fma2(w3, xd3, acc[3][3]);
        }
        if (kt + 1 < KT) {
            const int nxt = cur ^ 1;
            sW[nxt][wc4 + 0][wr] = wfn.x;
            sW[nxt][wc4 + 1][wr] = wfn.y;
            sW[nxt][wc4 + 2][wr] = wfn.z;
            sW[nxt][wc4 + 3][wr] = wfn.w;
            *(float4*)&sX[nxt][xr0][xc]     = xf0n;
            *(float4*)&sX[nxt][xr0 + 8][xc] = xf1n;
        }
        __syncthreads();
    }

#pragma unroll
    for (int p = 0; p < 4; p++) {
        int n_lo = n0 + nb + 2 * p;
        float blo = bias[n_lo], bhi = bias[n_lo + 1];
#pragma unroll
        for (int j = 0; j < 4; j++) {
            float lo = __uint_as_float((unsigned)(acc[p][j] & 0xffffffffu));
            float hi = __uint_as_float((unsigned)(acc[p][j] >> 32));
            long m = m0 + mb + j;
            Y[(long)n_lo * HWSZ + m]       = lo + blo;
            Y[(long)(n_lo + 1) * HWSZ + m] = hi + bhi;
        }
    }
}

// Fused slide attention, v2: one lane = one channel, depthwise weights in
// registers, cross-channel logit reduction via shfl.xor.
// Block = 128 threads (4 warps), handles (b, head, 8-row tile).
// Lane layout: lane = p4*8 + c  (c = channel 0..7, p4 = position-in-quad).
__global__ __launch_bounds__(128) void attn_kernel(
    const float* __restrict__ qkv,  // (B, 192, 4096)
    const float* __restrict__ w1,   // (72, 9)
    const float* __restrict__ dcb,  // (72)
    const float* __restrict__ dc1b, // (72)
    const float* __restrict__ rpb,  // (NH*9)
    float* __restrict__ y)          // (B, 64, 4096)
{
    const int b  = blockIdx.z;
    const int hd = blockIdx.y;
    const int h0 = blockIdx.x * 8;

    __shared__ float sk[10][66][8];
    __shared__ float sv[10][66][8];

    const int tid  = threadIdx.x;
    const int lane = tid & 31;
    const int warp = tid >> 5;
    const int c    = lane & 7;
    const int p4   = lane >> 3;

    const float* base = qkv + ((long)b * NQKV + hd * 24) * HWSZ;

    // halo tiles: k (ch 8..15), v (ch 16..23), zero pad
    for (int j = tid; j < 660; j += 128) {
        int yy = j / 66;
        int xx = j - yy * 66;
        int gh = h0 + yy - 1;
        int gw = xx - 1;
        bool ok = (gh >= 0 && gh < 64 && gw >= 0 && gw < 64);
        long off = ok ? ((long)8 * HWSZ + gh * 64 + gw) : 0;
#pragma unroll
        for (int c2 = 0; c2 < 8; c2++) {
            float kk = ok ? base[off + (long)c2 * HWSZ] : 0.f;
            float vv = ok ? base[off + (long)(8 + c2) * HWSZ] : 0.f;
            sk[yy][xx][c2] = kk;
            sv[yy][xx][c2] = vv;
        }
    }

    // per-lane channel weights + biases into registers
    float wreg[81];
    const float* wp = w1 + c * 81;
#pragma unroll
    for (int i = 0; i < 81; i++) wreg[i] = __ldg(&wp[i]);
    float bk[9], bv[9];
#pragma unroll
    for (int t = 0; t < 9; t++) {
        float base_b = __ldg(&dcb[c * 9 + t]) + __ldg(&dc1b[c * 9 + t]);
        bv[t] = base_b;
        bk[t] = base_b + __ldg(&rpb[hd * 9 + t]);  // rpb folded (added once per channel)
    }
    __syncthreads();

    // 512 positions, 16 per step (4 warps x 4 positions)
    for (int step = 0; step < 32; step++) {
        int pos = step * 16 + warp * 4 + p4;
        int hl  = pos >> 6;
        int w   = pos & 63;
        int hw  = (h0 + hl) * 64 + w;

        float q = base[(long)c * HWSZ + hw] * SCALEF;

        // k neighborhood
        float nk[9];
#pragma unroll
        for (int ty = 0; ty < 3; ty++)
#pragma unroll
            for (int tx = 0; tx < 3; tx++)
                nk[ty * 3 + tx] = sk[hl + ty][w + tx][c];

        float lg[9];
#pragma unroll
        for (int t = 0; t < 9; t++) {
            float kv = nk[t] + bk[t];
#pragma unroll
            for (int i = 0; i < 9; i++) kv += wreg[t * 9 + i] * nk[i];
            lg[t] = q * kv;
        }

        // reduce over channels (lanes differing in low 3 bits)
#pragma unroll
        for (int off = 4; off >= 1; off >>= 1)
#pragma unroll
            for (int t = 0; t < 9; t++)
                lg[t] += __shfl_xor_sync(0xffffffffu, lg[t], off);

        // softmax over 9 taps
        float m = lg[0];
#pragma unroll
        for (int t = 1; t < 9; t++) m = fmaxf(m, lg[t]);
        float at[9], s = 0.f;
#pragma unroll
        for (int t = 0; t < 9; t++) { at[t] = __expf(lg[t] - m); s += at[t]; }
        float inv = 1.f / s;

        // v neighborhood + weighted sum
        float nv[9];
#pragma unroll
        for (int ty = 0; ty < 3; ty++)
#pragma unroll
            for (int tx = 0; tx < 3; tx++)
                nv[ty * 3 + tx] = sv[hl + ty][w + tx][c];

        float o = 0.f;
#pragma unroll
        for (int t = 0; t < 9; t++) {
            float vv = nv[t] + bv[t];
#pragma unroll
            for (int i = 0; i < 9; i++) vv += wreg[t * 9 + i] * nv[i];
            o += at[t] * vv;
        }
        o *= inv;

        y[((long)b * CRN + hd * 8 + c) * HWSZ + hw] = o;
    }
}

extern "C" void kernel_launch(void* const* d_in, const int* in_sizes, int n_in,
                              void* d_out, int out_size) {
    const float* x      = (const float*)d_in[0];
    const float* qkv_w  = (const float*)d_in[5];
    const float* qkv_b  = (const float*)d_in[6];
    const float* dcb    = (const float*)d_in[7];
    const float* w1     = (const float*)d_in[8];
    const float* dc1b   = (const float*)d_in[9];
    const float* rpb    = (const float*)d_in[10];
    const float* proj_w = (const float*)d_in[11];
    const float* proj_b = (const float*)d_in[12];
    float* out = (float*)d_out;

    float *qkv = nullptr, *y = nullptr;
    cudaGetSymbolAddress((void**)&qkv, g_qkv);
    cudaGetSymbolAddress((void**)&y, g_y);

    gemm_kernel<<<dim3(HWSZ / 128, NQKV / 64, BB), 256>>>(
        qkv_w, x, qkv_b, qkv, DIMC, (long)DIMC * HWSZ, (long)NQKV * HWSZ);

    attn_kernel<<<dim3(8, NHD, BB), 128>>>(qkv, w1, dcb, dc1b, rpb, y);

    gemm_kernel<<<dim3(HWSZ / 128, DIMC / 64, BB), 256>>>(
        proj_w, y, proj_b, out, CRN, (long)CRN * HWSZ, (long)DIMC * HWSZ);
}

// round 3
// speedup vs baseline: 2.0282x; 1.0240x over previous
#include <cuda_runtime.h>

#define BB    16
#define HWSZ  4096
#define DIMC  256
#define NQKV  192
#define NHD   8
#define CRN   64
#define SCALEF 0.17677669529663687f

#define PLANE 364   // words per channel plane (10 rows x 36, padded; 364 % 32 = 12)
#define RSTR  36    // row stride in words

typedef unsigned long long ull;

__device__ float g_qkv[BB * NQKV * HWSZ];   // (B, 192, 4096)
__device__ float g_y  [BB * CRN  * HWSZ];   // (B, 64, 4096)

__device__ __forceinline__ ull fma2(ull a, ull b, ull c) {
    ull d;
    asm("fma.rn.f32x2 %0, %1, %2, %3;" : "=l"(d) : "l"(a), "l"(b), "l"(c));
    return d;
}
__device__ __forceinline__ ull add2(ull a, ull b) {
    ull d;
    asm("add.rn.f32x2 %0, %1, %2;" : "=l"(d) : "l"(a), "l"(b));
    return d;
}
__device__ __forceinline__ ull mul2(ull a, ull b) {
    ull d;
    asm("mul.rn.f32x2 %0, %1, %2;" : "=l"(d) : "l"(a), "l"(b));
    return d;
}
__device__ __forceinline__ ull pack2(float lo, float hi) {
    ull d;
    asm("mov.b64 %0, {%1, %2};" : "=l"(d)
        : "r"(__float_as_uint(lo)), "r"(__float_as_uint(hi)));
    return d;
}
__device__ __forceinline__ float lo32(ull v) {
    return __uint_as_float((unsigned)(v & 0xffffffffu));
}
__device__ __forceinline__ float hi32(ull v) {
    return __uint_as_float((unsigned)(v >> 32));
}
__device__ __forceinline__ void cp16(void* smem, const void* g) {
    unsigned s = (unsigned)__cvta_generic_to_shared(smem);
    asm volatile("cp.async.cg.shared.global [%0], [%1], 16;" :: "r"(s), "l"(g));
}
__device__ __forceinline__ void cp_commit() {
    asm volatile("cp.async.commit_group;");
}
__device__ __forceinline__ void cp_wait0() {
    asm volatile("cp.async.wait_group 0;");
}

// C(N x 4096) = W(N x K) * X(K x 4096) + bias, per batch (grid.z).
// 64(n) x 128(m) tile, BK=16, cp.async double-buffered, f32x2 FMA pairs along n.
__global__ __launch_bounds__(256, 3) void gemm_kernel(
    const float* __restrict__ Wm,
    const float* __restrict__ Xm,
    const float* __restrict__ bias,
    float* __restrict__ Ym,
    int K, long xStride, long yStride)
{
    const int b  = blockIdx.z;
    const int n0 = blockIdx.y * 64;
    const int m0 = blockIdx.x * 128;
    const float* X = Xm + (long)b * xStride;
    float*       Y = Ym + (long)b * yStride;

    __shared__ float sW[2][16][68];
    __shared__ float sX[2][16][128];

    const int tid  = threadIdx.x;
    const int lane = tid & 31;
    const int warp = tid >> 5;
    const int nb   = warp * 8;
    const int mb   = lane * 4;

    const int wr  = tid >> 2;
    const int wc4 = (tid & 3) * 4;
    const int xr0 = tid >> 5;
    const int xc  = (tid & 31) * 4;

    ull acc[4][4];
#pragma unroll
    for (int p = 0; p < 4; p++)
#pragma unroll
        for (int j = 0; j < 4; j++) acc[p][j] = 0ULL;

    const int KT = K / 16;

    // prologue: tile 0
    {
        cp16(&sX[0][xr0][xc],     &X[(long)(xr0)     * HWSZ + m0 + xc]);
        cp16(&sX[0][xr0 + 8][xc], &X[(long)(xr0 + 8) * HWSZ + m0 + xc]);
        cp_commit();
        float4 wf = *(const float4*)&Wm[(long)(n0 + wr) * K + wc4];
        sW[0][wc4 + 0][wr] = wf.x;
        sW[0][wc4 + 1][wr] = wf.y;
        sW[0][wc4 + 2][wr] = wf.z;
        sW[0][wc4 + 3][wr] = wf.w;
        cp_wait0();
    }
    __syncthreads();

    for (int kt = 0; kt < KT; kt++) {
        const int cur = kt & 1;
        const int nxt = cur ^ 1;
        float4 wfn;
        const bool more = (kt + 1 < KT);
        if (more) {
            int k0 = (kt + 1) * 16;
            cp16(&sX[nxt][xr0][xc],     &X[(long)(k0 + xr0)     * HWSZ + m0 + xc]);
            cp16(&sX[nxt][xr0 + 8][xc], &X[(long)(k0 + xr0 + 8) * HWSZ + m0 + xc]);
            cp_commit();
            wfn = *(const float4*)&Wm[(long)(n0 + wr) * K + k0 + wc4];
        }
#pragma unroll
        for (int k = 0; k < 16; k++) {
            float4 xv = *(const float4*)&sX[cur][k][mb];
            ull xd0 = pack2(xv.x, xv.x);
            ull xd1 = pack2(xv.y, xv.y);
            ull xd2 = pack2(xv.z, xv.z);
            ull xd3 = pack2(xv.w, xv.w);
            const ull* wrow = (const ull*)&sW[cur][k][nb];
            ull w0 = wrow[0], w1 = wrow[1], w2 = wrow[2], w3 = wrow[3];
            acc[0][0] = fma2(w0, xd0, acc[0][0]);
            acc[0][1] = fma2(w0, xd1, acc[0][1]);
            acc[0][2] = fma2(w0, xd2, acc[0][2]);
            acc[0][3] = fma2(w0, xd3, acc[0][3]);
            acc[1][0] = fma2(w1, xd0, acc[1][0]);
            acc[1][1] = fma2(w1, xd1, acc[1][1]);
            acc[1][2] = fma2(w1, xd2, acc[1][2]);
            acc[1][3] = fma2(w1, xd3, acc[1][3]);
            acc[2][0] = fma2(w2, xd0, acc[2][0]);
            acc[2][1] = fma2(w2, xd1, acc[2][1]);
            acc[2][2] = fma2(w2, xd2, acc[2][2]);
            acc[2][3] = fma2(w2, xd3, acc[2][3]);
            acc[3][0] = fma2(w3, xd0, acc[3][0]);
            acc[3][1] = fma2(w3, xd1, acc[3][1]);
            acc[3][2] = fma2(w3, xd2, acc[3][2]);
            acc[3][3] = fma2(w3, xd3, acc[3][3]);
        }
        if (more) {
            sW[nxt][wc4 + 0][wr] = wfn.x;
            sW[nxt][wc4 + 1][wr] = wfn.y;
            sW[nxt][wc4 + 2][wr] = wfn.z;
            sW[nxt][wc4 + 3][wr] = wfn.w;
            cp_wait0();
        }
        __syncthreads();
    }

#pragma unroll
    for (int p = 0; p < 4; p++) {
        int n_lo = n0 + nb + 2 * p;
        float blo = bias[n_lo], bhi = bias[n_lo + 1];
#pragma unroll
        for (int j = 0; j < 4; j++) {
            float lo = lo32(acc[p][j]);
            float hi = hi32(acc[p][j]);
            long m = m0 + mb + j;
            Y[(long)n_lo * HWSZ + m]       = lo + blo;
            Y[(long)(n_lo + 1) * HWSZ + m] = hi + bhi;
        }
    }
}

// Fused slide attention, v3: one lane = one channel x 4 consecutive positions
// packed as two f32x2 pairs. Depthwise weights pre-paired in smem.
// Block = 128 threads; covers (b, head, 8 rows x 32 cols).
__global__ __launch_bounds__(128) void attn_kernel(
    const float* __restrict__ qkv,  // (B, 192, 4096)
    const float* __restrict__ w1,   // (72, 9)
    const float* __restrict__ dcb,  // (72)
    const float* __restrict__ dc1b, // (72)
    const float* __restrict__ rpb,  // (NH*9)
    float* __restrict__ y)          // (B, 64, 4096)
{
    const int b   = blockIdx.z;
    const int hd  = blockIdx.y;
    const int rt  = blockIdx.x >> 1;
    const int ct  = blockIdx.x & 1;
    const int h0  = rt * 8;
    const int gw0 = ct * 32;

    __shared__ float sk[8 * PLANE];
    __shared__ float sv[8 * PLANE];
    __shared__ ull   sw2[8][81];
    __shared__ ull   sbk2[8][9];
    __shared__ ull   sbv2[8][9];

    const int tid  = threadIdx.x;
    const int lane = tid & 31;
    const int warp = tid >> 5;
    const int c    = lane & 7;
    const int g    = lane >> 3;

    const float* base = qkv + ((long)b * NQKV + hd * 24) * HWSZ;

    // paired depthwise weights
    for (int i = tid; i < 648; i += 128) {
        int cc = i / 81, idx = i - cc * 81;
        float w = w1[cc * 81 + idx];
        sw2[cc][idx] = pack2(w, w);
    }
    // paired biases (rpb folded into k bias)
    for (int i = tid; i < 72; i += 128) {
        int cc = i / 9, t = i - cc * 9;
        float bb = dcb[i] + dc1b[i];
        sbv2[cc][t] = pack2(bb, bb);
        float bk = bb + rpb[hd * 9 + t];
        sbk2[cc][t] = pack2(bk, bk);
    }
    // halo tiles: k (ch 8..15), v (ch 16..23), zero pad, [c][10][36] layout
    for (int i = tid; i < 8 * 340; i += 128) {
        int cc = i / 340, rem = i - cc * 340;
        int yy = rem / 34, xx = rem - yy * 34;
        int gh = h0 + yy - 1;
        int gx = gw0 + xx - 1;
        float kk = 0.f, vv = 0.f;
        if (gh >= 0 && gh < 64 && gx >= 0 && gx < 64) {
            long off = (long)(8 + cc) * HWSZ + gh * 64 + gx;
            kk = base[off];
            vv = base[off + 8 * HWSZ];
        }
        sk[cc * PLANE + yy * RSTR + xx] = kk;
        sv[cc * PLANE + yy * RSTR + xx] = vv;
    }
    __syncthreads();

    const ull* wrow = sw2[c];

#pragma unroll 1
    for (int step = 0; step < 4; step++) {
        const int task = step * 4 + warp;  // 0..15
        const int row  = task >> 1;        // 0..7
        const int half = task & 1;
        const int w0   = half * 16 + g * 4;  // local col 0..28, mult of 4
        const int hw   = (h0 + row) * 64 + gw0 + w0;

        // q for 4 positions
        float4 qv = *(const float4*)&base[(long)c * HWSZ + hw];
        ull q0 = pack2(qv.x * SCALEF, qv.y * SCALEF);
        ull q1 = pack2(qv.z * SCALEF, qv.w * SCALEF);

        // k neighborhood: 3 rows x 6 cols -> 5 overlapping pairs per row
        ull nk[3][5];
        {
            const float* p = &sk[c * PLANE + row * RSTR + w0];
#pragma unroll
            for (int ty = 0; ty < 3; ty++) {
                float4 a  = *(const float4*)(p + ty * RSTR);
                float2 a2 = *(const float2*)(p + ty * RSTR + 4);
                nk[ty][0] = pack2(a.x, a.y);
                nk[ty][1] = pack2(a.y, a.z);
                nk[ty][2] = pack2(a.z, a.w);
                nk[ty][3] = pack2(a.w, a2.x);
                nk[ty][4] = pack2(a2.x, a2.y);
            }
        }

        ull lg0[9], lg1[9];
#pragma unroll
        for (int t = 0; t < 9; t++) {
            const int ty = t / 3, tx = t - ty * 3;
            ull bk  = sbk2[c][t];
            ull kv0 = add2(nk[ty][tx],     bk);
            ull kv1 = add2(nk[ty][tx + 2], bk);
#pragma unroll
            for (int i = 0; i < 9; i++) {
                const int iy = i / 3, ix = i - iy * 3;
                ull wp = wrow[t * 9 + i];
                kv0 = fma2(wp, nk[iy][ix],     kv0);
                kv1 = fma2(wp, nk[iy][ix + 2], kv1);
            }
            lg0[t] = mul2(q0, kv0);
            lg1[t] = mul2(q1, kv1);
        }

        // cross-channel reduce (lanes differ in low 3 bits)
        float lf[4][9];
#pragma unroll
        for (int t = 0; t < 9; t++) {
            lf[0][t] = lo32(lg0[t]); lf[1][t] = hi32(lg0[t]);
            lf[2][t] = lo32(lg1[t]); lf[3][t] = hi32(lg1[t]);
        }
#pragma unroll
        for (int off = 4; off >= 1; off >>= 1)
#pragma unroll
            for (int p = 0; p < 4; p++)
#pragma unroll
                for (int t = 0; t < 9; t++)
                    lf[p][t] += __shfl_xor_sync(0xffffffffu, lf[p][t], off);

        // softmax per position, in place
#pragma unroll
        for (int p = 0; p < 4; p++) {
            float m = lf[p][0];
#pragma unroll
            for (int t = 1; t < 9; t++) m = fmaxf(m, lf[p][t]);
            float s = 0.f;
#pragma unroll
            for (int t = 0; t < 9; t++) { lf[p][t] = __expf(lf[p][t] - m); s += lf[p][t]; }
            float inv = 1.f / s;
#pragma unroll
            for (int t = 0; t < 9; t++) lf[p][t] *= inv;
        }

        // v pass
        ull nv[3][5];
        {
            const float* p = &sv[c * PLANE + row * RSTR + w0];
#pragma unroll
            for (int ty = 0; ty < 3; ty++) {
                float4 a  = *(const float4*)(p + ty * RSTR);
                float2 a2 = *(const float2*)(p + ty * RSTR + 4);
                nv[ty][0] = pack2(a.x, a.y);
                nv[ty][1] = pack2(a.y, a.z);
                nv[ty][2] = pack2(a.z, a.w);
                nv[ty][3] = pack2(a.w, a2.x);
                nv[ty][4] = pack2(a2.x, a2.y);
            }
        }
        float o0 = 0.f, o1 = 0.f, o2 = 0.f, o3 = 0.f;
#pragma unroll
        for (int t = 0; t < 9; t++) {
            const int ty = t / 3, tx = t - ty * 3;
            ull bv  = sbv2[c][t];
            ull vv0 = add2(nv[ty][tx],     bv);
            ull vv1 = add2(nv[ty][tx + 2], bv);
#pragma unroll
            for (int i = 0; i < 9; i++) {
                const int iy = i / 3, ix = i - iy * 3;
                ull wp = wrow[t * 9 + i];
                vv0 = fma2(wp, nv[iy][ix],     vv0);
                vv1 = fma2(wp, nv[iy][ix + 2], vv1);
            }
            o0 += lf[0][t] * lo32(vv0);
            o1 += lf[1][t] * hi32(vv0);
            o2 += lf[2][t] * lo32(vv1);
            o3 += lf[3][t] * hi32(vv1);
        }
        *(float4*)&y[((long)b * CRN + hd * 8 + c) * HWSZ + hw] =
            make_float4(o0, o1, o2, o3);
    }
}

extern "C" void kernel_launch(void* const* d_in, const int* in_sizes, int n_in,
                              void* d_out, int out_size) {
    const float* x      = (const float*)d_in[0];
    const float* qkv_w  = (const float*)d_in[5];
    const float* qkv_b  = (const float*)d_in[6];
    const float* dcb    = (const float*)d_in[7];
    const float* w1     = (const float*)d_in[8];
    const float* dc1b   = (const float*)d_in[9];
    const float* rpb    = (const float*)d_in[10];
    const float* proj_w = (const float*)d_in[11];
    const float* proj_b = (const float*)d_in[12];
    float* out = (float*)d_out;

    float *qkv = nullptr, *yb = nullptr;
    cudaGetSymbolAddress((void**)&qkv, g_qkv);
    cudaGetSymbolAddress((void**)&yb, g_y);

    gemm_kernel<<<dim3(HWSZ / 128, NQKV / 64, BB), 256>>>(
        qkv_w, x, qkv_b, qkv, DIMC, (long)DIMC * HWSZ, (long)NQKV * HWSZ);

    attn_kernel<<<dim3(16, NHD, BB), 128>>>(qkv, w1, dcb, dc1b, rpb, yb);

    gemm_kernel<<<dim3(HWSZ / 128, DIMC / 64, BB), 256>>>(
        proj_w, yb, proj_b, out, CRN, (long)CRN * HWSZ, (long)DIMC * HWSZ);
}